// round 16
// baseline (speedup 1.0000x reference)
#include <cuda_runtime.h>

#define B_   32
#define T_   256
#define F_   64
#define C_   16
#define CO_  16
#define P_   64
#define S_   32
#define K_   4
#define FC   1024
#define KIN  1056
#define OUTC 96
#define ROWS (B_*T_)        // 8192
#define RSTR (F_*OUTC)      // 6144 floats per (b,t) row

#define KSLC 132            // k per octant (8 x 132 = 1056)
#define APAD 34             // Ad row stride in doubles
#define A_DBL (KSLC*APAD)   // 4488 doubles = 35904 B
#define GSMEM (A_DBL*8 + KSLC*64*4)   // 35904 + 33792 = 69696 B

// split-K8 partial sums (no bias/relu): 8 x 8192 x 64 fp32 = 16 MB
__device__ __align__(256) float g_part[8][ROWS][P_];

// ---------------- packed f32x2 helpers ----------------
__device__ __forceinline__ double pack2(float lo, float hi) {
    double d; asm("mov.b64 %0, {%1, %2};" : "=d"(d) : "f"(lo), "f"(hi)); return d;
}
__device__ __forceinline__ float2 unpack2(double d) {
    float2 v; asm("mov.b64 {%0, %1}, %2;" : "=f"(v.x), "=f"(v.y) : "d"(d)); return v;
}
__device__ __forceinline__ void fma2(double& acc, double a, double b) {
    asm("fma.rn.f32x2 %0, %1, %2, %3;" : "=d"(acc) : "d"(a), "d"(b), "d"(acc));
}

// ============================================================================
// K1 (primary): split-K8 point GEMM, single-stage: load WHOLE k-slice into
// smem once, one sync, then barrier-free compute. grid=2048 (256 tiles x 8
// octants), 128 thr, ~70KB dynamic smem (3 blocks/SM). BM=32, per-thread
// 4m x 4n (conflict-free LDS). Octant o covers k [132o, 132o+132).
// ============================================================================
__global__ __launch_bounds__(128)
void tpc_gemm(const float* __restrict__ x,
              const float* __restrict__ stat,
              const float* __restrict__ W_p)
{
    cudaTriggerProgrammaticLaunchCompletion();

    extern __shared__ __align__(16) char smem_raw[];
    double* Ad  = reinterpret_cast<double*>(smem_raw);            // [KSLC][APAD] dup doubles
    float*  Bsf = reinterpret_cast<float*>(smem_raw + A_DBL * 8); // [KSLC][64] natural

    const int tid  = threadIdx.x;
    const int tile = blockIdx.x >> 3;
    const int oct  = blockIdx.x & 7;
    const int row0 = tile * 32;
    const int b    = row0 >> 8;
    const int kg0  = oct * KSLC;               // multiple of 4

    // ---- load A slice: 32 rows x 33 float4 = 1056 float4 ----
    for (int idx = tid; idx < 32 * 33; idx += 128) {
        int r  = idx / 33;
        int kq = idx - r * 33;
        int kg = kg0 + kq * 4;
        float4 v;
        if (kg < FC)
            v = *reinterpret_cast<const float4*>(&x[(size_t)(row0 + r) * FC + kg]);
        else
            v = *reinterpret_cast<const float4*>(&stat[b * S_ + (kg - FC)]);
        double* row = Ad + (size_t)(kq * 4) * APAD + r;
        row[0 * APAD] = pack2(v.x, v.x);
        row[1 * APAD] = pack2(v.y, v.y);
        row[2 * APAD] = pack2(v.z, v.z);
        row[3 * APAD] = pack2(v.w, v.w);
    }
    // ---- load B slice: 132 kk x 16 float4 = 2112 float4 ----
    for (int idx = tid; idx < KSLC * 16; idx += 128) {
        int kk = idx >> 4;
        int nq = idx & 15;
        *reinterpret_cast<float4*>(&Bsf[kk * 64 + nq * 4]) =
            *reinterpret_cast<const float4*>(&W_p[(size_t)(kg0 + kk) * P_ + nq * 4]);
    }
    __syncthreads();                           // the only barrier

    const int m0 = (tid >> 4) * 4;
    const int n0 = (tid & 15) * 4;

    double acc[4][2];
    #pragma unroll
    for (int i = 0; i < 4; ++i) { acc[i][0] = 0.0; acc[i][1] = 0.0; }

    // ---- barrier-free compute over all 132 kk ----
    #pragma unroll 4
    for (int kk = 0; kk < KSLC; ++kk) {
        const double* arow = Ad + (size_t)kk * APAD;
        double2 a01 = *reinterpret_cast<const double2*>(arow + m0);
        double2 a23 = *reinterpret_cast<const double2*>(arow + m0 + 2);
        double2 bp  = *reinterpret_cast<const double2*>(&Bsf[kk * 64 + n0]);
        fma2(acc[0][0], a01.x, bp.x); fma2(acc[0][1], a01.x, bp.y);
        fma2(acc[1][0], a01.y, bp.x); fma2(acc[1][1], a01.y, bp.y);
        fma2(acc[2][0], a23.x, bp.x); fma2(acc[2][1], a23.x, bp.y);
        fma2(acc[3][0], a23.y, bp.x); fma2(acc[3][1], a23.y, bp.y);
    }

    #pragma unroll
    for (int m = 0; m < 4; ++m) {
        float2 p = unpack2(acc[m][0]);
        float2 q = unpack2(acc[m][1]);
        *reinterpret_cast<float4*>(&g_part[oct][row0 + m0 + m][n0]) =
            make_float4(p.x, p.y, q.x, q.y);
    }
}

// ============================================================================
// K2 (PDL secondary, independent of K1): conv per (b,f).
// Writes ch16..31 (conv+bias+relu) and ch0..15 (relu x). 2048 blocks.
// ============================================================================
__global__ __launch_bounds__(256, 4)
void tpc_conv(const float* __restrict__ x,
              const float* __restrict__ conv_w,
              const float* __restrict__ conv_b,
              float* __restrict__ out)
{
    __shared__ __align__(16) float xs[T_ + 6][17];
    __shared__ __align__(16) float ws[64][20];
    __shared__ float bsv[16];

    const int tid = threadIdx.x;
    const int b   = blockIdx.x >> 6;
    const int f   = blockIdx.x & 63;
    const size_t xrow0 = ((size_t)b * T_ * F_ + f) * C_;

    #pragma unroll
    for (int l = 0; l < 5; ++l) {
        int idx = tid + l * 256;
        if (idx < (T_ + 6) * 4) {
            int r = idx >> 2;
            int q = idx & 3;
            float4 v = make_float4(0.f, 0.f, 0.f, 0.f);
            if (r >= 6)
                v = *reinterpret_cast<const float4*>(&x[xrow0 + (size_t)(r - 6) * FC + q * 4]);
            xs[r][q * 4 + 0] = v.x;
            xs[r][q * 4 + 1] = v.y;
            xs[r][q * 4 + 2] = v.z;
            xs[r][q * 4 + 3] = v.w;
        }
    }
    {
        int co = tid >> 4;
        int c  = tid & 15;
        float4 w = *reinterpret_cast<const float4*>(&conv_w[((size_t)f * CO_ + co) * 64 + c * 4]);
        ws[c * 4 + 0][co] = w.x;
        ws[c * 4 + 1][co] = w.y;
        ws[c * 4 + 2][co] = w.z;
        ws[c * 4 + 3][co] = w.w;
    }
    if (tid < 16) bsv[tid] = conv_b[f * CO_ + tid];
    __syncthreads();

    const int t0  = (tid >> 2) * 4;
    const int co0 = (tid & 3) * 4;

    double acc[4][2];
    #pragma unroll
    for (int i = 0; i < 4; ++i) { acc[i][0] = 0.0; acc[i][1] = 0.0; }

    #pragma unroll 4
    for (int c = 0; c < C_; ++c) {
        double ad[10];
        #pragma unroll
        for (int r = 0; r < 10; ++r) {
            float a = xs[t0 + r][c];
            ad[r] = pack2(a, a);
        }
        #pragma unroll
        for (int k = 0; k < K_; ++k) {
            double2 w = *reinterpret_cast<const double2*>(&ws[c * 4 + k][co0]);
            #pragma unroll
            for (int i = 0; i < 4; ++i) {
                fma2(acc[i][0], ad[i + 2 * k], w.x);
                fma2(acc[i][1], ad[i + 2 * k], w.y);
            }
        }
    }

    float* ob = out + ((size_t)b * T_ * F_ + f) * OUTC;

    {
        float4 bb = *reinterpret_cast<const float4*>(&bsv[co0]);
        #pragma unroll
        for (int i = 0; i < 4; ++i) {
            float2 q0 = unpack2(acc[i][0]);
            float2 q1 = unpack2(acc[i][1]);
            float4 v = make_float4(fmaxf(q0.x + bb.x, 0.f), fmaxf(q0.y + bb.y, 0.f),
                                   fmaxf(q1.x + bb.z, 0.f), fmaxf(q1.y + bb.w, 0.f));
            *reinterpret_cast<float4*>(&ob[(size_t)(t0 + i) * RSTR + 16 + co0]) = v;
        }
    }

    #pragma unroll
    for (int l = 0; l < 4; ++l) {
        int idx = tid + l * 256;
        int t   = idx >> 2;
        int q   = idx & 3;
        float4 v = *reinterpret_cast<const float4*>(&x[xrow0 + (size_t)t * FC + q * 4]);
        v.x = fmaxf(v.x, 0.f); v.y = fmaxf(v.y, 0.f);
        v.z = fmaxf(v.z, 0.f); v.w = fmaxf(v.w, 0.f);
        *reinterpret_cast<float4*>(&ob[(size_t)t * RSTR + q * 4]) = v;
    }
}

// ============================================================================
// K3: broadcast. ch32..95 = relu(sum 8 partials + b_p) replicated across 64 f.
// ============================================================================
__global__ __launch_bounds__(256)
void tpc_bcast(const float* __restrict__ b_p, float* __restrict__ out)
{
    const int tid = threadIdx.x;
    const int q   = tid & 15;
    const int f0  = tid >> 4;
    const int row_base = blockIdx.x * 4;
    float4 bb = *reinterpret_cast<const float4*>(&b_p[q * 4]);

    #pragma unroll
    for (int rr = 0; rr < 4; ++rr) {
        int row = row_base + rr;
        float4 s = bb;
        #pragma unroll
        for (int o = 0; o < 8; ++o) {
            float4 v = *reinterpret_cast<const float4*>(&g_part[o][row][q * 4]);
            s.x += v.x; s.y += v.y; s.z += v.z; s.w += v.w;
        }
        float4 v = make_float4(fmaxf(s.x, 0.f), fmaxf(s.y, 0.f),
                               fmaxf(s.z, 0.f), fmaxf(s.w, 0.f));
        float* ob = out + (size_t)row * RSTR + 32 + q * 4;
        #pragma unroll
        for (int ff = 0; ff < 4; ++ff) {
            int f = ff * 16 + f0;
            *reinterpret_cast<float4*>(&ob[(size_t)f * OUTC]) = v;
        }
    }
}

extern "C" void kernel_launch(void* const* d_in, const int* in_sizes, int n_in,
                              void* d_out, int out_size)
{
    const float* x      = (const float*)d_in[0];   // [32,256,64,16]
    const float* statv  = (const float*)d_in[1];   // [32,32]
    const float* conv_w = (const float*)d_in[2];   // [64,16,16,4]
    const float* conv_b = (const float*)d_in[3];   // [64,16]
    const float* W_p    = (const float*)d_in[4];   // [1056,64]
    const float* b_p    = (const float*)d_in[5];   // [64]
    float* out = (float*)d_out;                    // [32,256,64,96]

    static bool attr_set = false;
    if (!attr_set) {
        cudaFuncSetAttribute(tpc_gemm, cudaFuncAttributeMaxDynamicSharedMemorySize, GSMEM);
        attr_set = true;
    }

    // K1: GEMM primary (PDL completion at entry)
    tpc_gemm<<<2048, 128, GSMEM>>>(x, statv, W_p);

    // K2: conv, PDL secondary — overlaps K1 (no dependency)
    {
        cudaLaunchConfig_t cfg = {};
        cfg.gridDim  = dim3(2048);
        cfg.blockDim = dim3(256);
        cfg.dynamicSmemBytes = 0;
        cfg.stream = 0;
        cudaLaunchAttribute attrs[1];
        attrs[0].id = cudaLaunchAttributeProgrammaticStreamSerialization;
        attrs[0].val.programmaticStreamSerializationAllowed = 1;
        cfg.attrs = attrs;
        cfg.numAttrs = 1;
        cudaLaunchKernelEx(&cfg, tpc_conv, x, conv_w, conv_b, (float*)d_out);
    }

    // K3: broadcast — waits for K1+K2 via stream order
    tpc_bcast<<<ROWS / 4, 256>>>(b_p, out);
}

// round 17
// speedup vs baseline: 1.2404x; 1.2404x over previous
#include <cuda_runtime.h>

#define B_   32
#define T_   256
#define F_   64
#define C_   16
#define CO_  16
#define P_   64
#define S_   32
#define K_   4
#define FC   1024
#define KIN  1056
#define OUTC 96
#define ROWS (B_*T_)        // 8192
#define RSTR (F_*OUTC)      // 6144 floats per (b,t) row

// split-K4 partial sums (no bias/relu): 4 x 8192 x 64 fp32 = 8 MB
__device__ __align__(256) float g_part[4][ROWS][P_];

// ---------------- packed f32x2 helpers ----------------
__device__ __forceinline__ double pack2(float lo, float hi) {
    double d; asm("mov.b64 %0, {%1, %2};" : "=d"(d) : "f"(lo), "f"(hi)); return d;
}
__device__ __forceinline__ float2 unpack2(double d) {
    float2 v; asm("mov.b64 {%0, %1}, %2;" : "=f"(v.x), "=f"(v.y) : "d"(d)); return v;
}
__device__ __forceinline__ void fma2(double& acc, double a, double b) {
    asm("fma.rn.f32x2 %0, %1, %2, %3;" : "=d"(acc) : "d"(a), "d"(b), "d"(acc));
}

// ============================================================================
// K1 (primary): split-K4 point GEMM. grid=1024 (256 tiles x 4 quarters),
// 256 thr (8 warps), <=64 regs -> 4 blocks/SM = 32 warps/SM.
// BM=32, BN=64, BK=32, per-thread 2m x 4n: 2 LDS : 4 FMA2 per kk,
// register prefetch of the next tile. Conflict-free LDS patterns.
// ============================================================================
__global__ __launch_bounds__(256, 4)
void tpc_gemm(const float* __restrict__ x,
              const float* __restrict__ stat,
              const float* __restrict__ W_p)
{
    cudaTriggerProgrammaticLaunchCompletion();

    __shared__ __align__(16) double Ad[32][34];   // [kk][m] dup doubles
    __shared__ __align__(16) float  Bsf[32][64];  // [kk][n] natural pairs

    const int tid     = threadIdx.x;
    const int tile    = blockIdx.x >> 2;
    const int quarter = blockIdx.x & 3;
    const int row0    = tile * 32;
    const int b       = row0 >> 8;

    const int kb0 = (quarter == 0) ? 0 : (9 + 8 * (quarter - 1));   // {0,9,17,25}
    const int kbE = 9 + 8 * quarter;                                 // {9,17,25,33}

    const int m0  = (tid >> 4) * 2;       // 16 m-pairs
    const int n0  = (tid & 15) * 4;       // 16 n-quads

    // loader indices: A 256 float4 (1/thread), B 512 float4 (2/thread)
    const int ar  = tid >> 3;             // 0..31
    const int akq = tid & 7;
    const int bkk = tid >> 4;             // 0..15 (two halves)
    const int bnq = tid & 15;

    double acc00 = 0.0, acc01 = 0.0, acc10 = 0.0, acc11 = 0.0;
    float4 pa, pb0, pb1;

    // prefetch first tile (kb0*32 + 31 < 1024 for all quarters -> x only)
    pa  = *reinterpret_cast<const float4*>(&x[(size_t)(row0 + ar) * FC + kb0 * 32 + akq * 4]);
    pb0 = *reinterpret_cast<const float4*>(&W_p[(size_t)(kb0 * 32 + bkk) * P_ + bnq * 4]);
    pb1 = *reinterpret_cast<const float4*>(&W_p[(size_t)(kb0 * 32 + bkk + 16) * P_ + bnq * 4]);

    for (int kb = kb0; kb < kbE; ++kb) {
        // commit prefetched tile
        Ad[akq * 4 + 0][ar] = pack2(pa.x, pa.x);
        Ad[akq * 4 + 1][ar] = pack2(pa.y, pa.y);
        Ad[akq * 4 + 2][ar] = pack2(pa.z, pa.z);
        Ad[akq * 4 + 3][ar] = pack2(pa.w, pa.w);
        *reinterpret_cast<float4*>(&Bsf[bkk][bnq * 4])      = pb0;
        *reinterpret_cast<float4*>(&Bsf[bkk + 16][bnq * 4]) = pb1;
        __syncthreads();

        // prefetch next tile during compute
        if (kb + 1 < kbE) {
            int kg0 = (kb + 1) * 32;
            int kgf = kg0 + akq * 4;
            if (kgf < FC)
                pa = *reinterpret_cast<const float4*>(&x[(size_t)(row0 + ar) * FC + kgf]);
            else
                pa = *reinterpret_cast<const float4*>(&stat[b * S_ + (kgf - FC)]);
            pb0 = *reinterpret_cast<const float4*>(&W_p[(size_t)(kg0 + bkk) * P_ + bnq * 4]);
            pb1 = *reinterpret_cast<const float4*>(&W_p[(size_t)(kg0 + bkk + 16) * P_ + bnq * 4]);
        }

        #pragma unroll
        for (int kk = 0; kk < 32; ++kk) {
            double2 aa = *reinterpret_cast<const double2*>(&Ad[kk][m0]);   // broadcast
            double2 bp = *reinterpret_cast<const double2*>(&Bsf[kk][n0]);  // conflict-free
            fma2(acc00, aa.x, bp.x); fma2(acc01, aa.x, bp.y);
            fma2(acc10, aa.y, bp.x); fma2(acc11, aa.y, bp.y);
        }
        __syncthreads();
    }

    // store raw partials: 2 rows x 4 floats per thread
    {
        float2 p0 = unpack2(acc00);
        float2 p1 = unpack2(acc01);
        *reinterpret_cast<float4*>(&g_part[quarter][row0 + m0][n0]) =
            make_float4(p0.x, p0.y, p1.x, p1.y);
        float2 q0 = unpack2(acc10);
        float2 q1 = unpack2(acc11);
        *reinterpret_cast<float4*>(&g_part[quarter][row0 + m0 + 1][n0]) =
            make_float4(q0.x, q0.y, q1.x, q1.y);
    }
}

// ============================================================================
// K2 (PDL secondary, independent of K1): conv per (b,f).
// Writes ch16..31 (conv+bias+relu) and ch0..15 (relu x). 2048 blocks.
// ============================================================================
__global__ __launch_bounds__(256, 4)
void tpc_conv(const float* __restrict__ x,
              const float* __restrict__ conv_w,
              const float* __restrict__ conv_b,
              float* __restrict__ out)
{
    __shared__ __align__(16) float xs[T_ + 6][17];
    __shared__ __align__(16) float ws[64][20];
    __shared__ float bsv[16];

    const int tid = threadIdx.x;
    const int b   = blockIdx.x >> 6;
    const int f   = blockIdx.x & 63;
    const size_t xrow0 = ((size_t)b * T_ * F_ + f) * C_;

    #pragma unroll
    for (int l = 0; l < 5; ++l) {
        int idx = tid + l * 256;
        if (idx < (T_ + 6) * 4) {
            int r = idx >> 2;
            int q = idx & 3;
            float4 v = make_float4(0.f, 0.f, 0.f, 0.f);
            if (r >= 6)
                v = *reinterpret_cast<const float4*>(&x[xrow0 + (size_t)(r - 6) * FC + q * 4]);
            xs[r][q * 4 + 0] = v.x;
            xs[r][q * 4 + 1] = v.y;
            xs[r][q * 4 + 2] = v.z;
            xs[r][q * 4 + 3] = v.w;
        }
    }
    {
        int co = tid >> 4;
        int c  = tid & 15;
        float4 w = *reinterpret_cast<const float4*>(&conv_w[((size_t)f * CO_ + co) * 64 + c * 4]);
        ws[c * 4 + 0][co] = w.x;
        ws[c * 4 + 1][co] = w.y;
        ws[c * 4 + 2][co] = w.z;
        ws[c * 4 + 3][co] = w.w;
    }
    if (tid < 16) bsv[tid] = conv_b[f * CO_ + tid];
    __syncthreads();

    const int t0  = (tid >> 2) * 4;
    const int co0 = (tid & 3) * 4;

    double acc[4][2];
    #pragma unroll
    for (int i = 0; i < 4; ++i) { acc[i][0] = 0.0; acc[i][1] = 0.0; }

    #pragma unroll 4
    for (int c = 0; c < C_; ++c) {
        double ad[10];
        #pragma unroll
        for (int r = 0; r < 10; ++r) {
            float a = xs[t0 + r][c];
            ad[r] = pack2(a, a);
        }
        #pragma unroll
        for (int k = 0; k < K_; ++k) {
            double2 w = *reinterpret_cast<const double2*>(&ws[c * 4 + k][co0]);
            #pragma unroll
            for (int i = 0; i < 4; ++i) {
                fma2(acc[i][0], ad[i + 2 * k], w.x);
                fma2(acc[i][1], ad[i + 2 * k], w.y);
            }
        }
    }

    float* ob = out + ((size_t)b * T_ * F_ + f) * OUTC;

    {
        float4 bb = *reinterpret_cast<const float4*>(&bsv[co0]);
        #pragma unroll
        for (int i = 0; i < 4; ++i) {
            float2 q0 = unpack2(acc[i][0]);
            float2 q1 = unpack2(acc[i][1]);
            float4 v = make_float4(fmaxf(q0.x + bb.x, 0.f), fmaxf(q0.y + bb.y, 0.f),
                                   fmaxf(q1.x + bb.z, 0.f), fmaxf(q1.y + bb.w, 0.f));
            *reinterpret_cast<float4*>(&ob[(size_t)(t0 + i) * RSTR + 16 + co0]) = v;
        }
    }

    #pragma unroll
    for (int l = 0; l < 4; ++l) {
        int idx = tid + l * 256;
        int t   = idx >> 2;
        int q   = idx & 3;
        float4 v = *reinterpret_cast<const float4*>(&x[xrow0 + (size_t)t * FC + q * 4]);
        v.x = fmaxf(v.x, 0.f); v.y = fmaxf(v.y, 0.f);
        v.z = fmaxf(v.z, 0.f); v.w = fmaxf(v.w, 0.f);
        *reinterpret_cast<float4*>(&ob[(size_t)t * RSTR + q * 4]) = v;
    }
}

// ============================================================================
// K3: broadcast. ch32..95 = relu(sum 4 partials + b_p) replicated across 64 f.
// Normal launch: stream order guarantees K1 and K2 are complete.
// ============================================================================
__global__ __launch_bounds__(256)
void tpc_bcast(const float* __restrict__ b_p, float* __restrict__ out)
{
    const int tid = threadIdx.x;
    const int q   = tid & 15;
    const int f0  = tid >> 4;
    const int row_base = blockIdx.x * 4;
    float4 bb = *reinterpret_cast<const float4*>(&b_p[q * 4]);

    #pragma unroll
    for (int rr = 0; rr < 4; ++rr) {
        int row = row_base + rr;
        float4 v0 = *reinterpret_cast<const float4*>(&g_part[0][row][q * 4]);
        float4 v1 = *reinterpret_cast<const float4*>(&g_part[1][row][q * 4]);
        float4 v2 = *reinterpret_cast<const float4*>(&g_part[2][row][q * 4]);
        float4 v3 = *reinterpret_cast<const float4*>(&g_part[3][row][q * 4]);
        float4 v;
        v.x = fmaxf((v0.x + v1.x) + (v2.x + v3.x) + bb.x, 0.f);
        v.y = fmaxf((v0.y + v1.y) + (v2.y + v3.y) + bb.y, 0.f);
        v.z = fmaxf((v0.z + v1.z) + (v2.z + v3.z) + bb.z, 0.f);
        v.w = fmaxf((v0.w + v1.w) + (v2.w + v3.w) + bb.w, 0.f);
        float* ob = out + (size_t)row * RSTR + 32 + q * 4;
        #pragma unroll
        for (int ff = 0; ff < 4; ++ff) {
            int f = ff * 16 + f0;
            *reinterpret_cast<float4*>(&ob[(size_t)f * OUTC]) = v;
        }
    }
}

extern "C" void kernel_launch(void* const* d_in, const int* in_sizes, int n_in,
                              void* d_out, int out_size)
{
    const float* x      = (const float*)d_in[0];   // [32,256,64,16]
    const float* statv  = (const float*)d_in[1];   // [32,32]
    const float* conv_w = (const float*)d_in[2];   // [64,16,16,4]
    const float* conv_b = (const float*)d_in[3];   // [64,16]
    const float* W_p    = (const float*)d_in[4];   // [1056,64]
    const float* b_p    = (const float*)d_in[5];   // [64]
    float* out = (float*)d_out;                    // [32,256,64,96]

    // K1: GEMM primary (PDL completion at entry)
    tpc_gemm<<<1024, 256>>>(x, statv, W_p);

    // K2: conv, PDL secondary — may overlap K1 (no dependency)
    {
        cudaLaunchConfig_t cfg = {};
        cfg.gridDim  = dim3(2048);
        cfg.blockDim = dim3(256);
        cfg.dynamicSmemBytes = 0;
        cfg.stream = 0;
        cudaLaunchAttribute attrs[1];
        attrs[0].id = cudaLaunchAttributeProgrammaticStreamSerialization;
        attrs[0].val.programmaticStreamSerializationAllowed = 1;
        cfg.attrs = attrs;
        cfg.numAttrs = 1;
        cudaLaunchKernelEx(&cfg, tpc_conv, x, conv_w, conv_b, (float*)d_out);
    }

    // K3: broadcast — waits for K1+K2 via stream order
    tpc_bcast<<<ROWS / 4, 256>>>(b_p, out);
}